// round 1
// baseline (speedup 1.0000x reference)
#include <cuda_runtime.h>
#include <math.h>

#define B_  4
#define L_  2048
#define D_  2048
#define H_  16
#define HD_ 128
#define M_  (B_ * L_)   // 8192 rows
#define E3_ (3 * D_)    // 6144

// Scratch (allocation-free rule: __device__ globals)
__device__ float g_qkv[(size_t)M_ * E3_];  // 201 MB
__device__ float g_y[(size_t)M_ * D_];     // 64 MB

// ---------------------------------------------------------------------------
// GEMM: C[M,N] = A[M,K] * B[N,K]^T   (both operands K-major, matches 'bld,ed->ble')
// 128x128 block, BK=8, 256 threads, 8x8 register micro-tile.
// ---------------------------------------------------------------------------
__global__ __launch_bounds__(256) void sgemm_nt(const float* __restrict__ A,
                                                const float* __restrict__ B,
                                                float* __restrict__ C,
                                                int M, int N, int K)
{
    __shared__ float As[8][128];
    __shared__ float Bs[8][128];

    const int bm  = blockIdx.y * 128;
    const int bn  = blockIdx.x * 128;
    const int tid = threadIdx.x;
    const int tx  = tid & 15;        // 0..15  -> N direction
    const int ty  = tid >> 4;        // 0..15  -> M direction
    const int lrow = tid >> 1;       // 0..127
    const int lseg = (tid & 1) * 4;  // 0 or 4

    const float* Ap = A + (size_t)(bm + lrow) * K + lseg;
    const float* Bp = B + (size_t)(bn + lrow) * K + lseg;

    float acc[8][8];
    #pragma unroll
    for (int i = 0; i < 8; i++)
        #pragma unroll
        for (int j = 0; j < 8; j++) acc[i][j] = 0.f;

    for (int k0 = 0; k0 < K; k0 += 8) {
        float4 a4 = *(const float4*)(Ap + k0);
        float4 b4 = *(const float4*)(Bp + k0);
        As[lseg + 0][lrow] = a4.x; As[lseg + 1][lrow] = a4.y;
        As[lseg + 2][lrow] = a4.z; As[lseg + 3][lrow] = a4.w;
        Bs[lseg + 0][lrow] = b4.x; Bs[lseg + 1][lrow] = b4.y;
        Bs[lseg + 2][lrow] = b4.z; Bs[lseg + 3][lrow] = b4.w;
        __syncthreads();

        #pragma unroll
        for (int kk = 0; kk < 8; kk++) {
            float4 a0 = *(const float4*)&As[kk][ty * 8];
            float4 a1 = *(const float4*)&As[kk][ty * 8 + 4];
            float4 b0 = *(const float4*)&Bs[kk][tx * 8];
            float4 b1 = *(const float4*)&Bs[kk][tx * 8 + 4];
            float a[8] = {a0.x, a0.y, a0.z, a0.w, a1.x, a1.y, a1.z, a1.w};
            float b[8] = {b0.x, b0.y, b0.z, b0.w, b1.x, b1.y, b1.z, b1.w};
            #pragma unroll
            for (int i = 0; i < 8; i++)
                #pragma unroll
                for (int j = 0; j < 8; j++)
                    acc[i][j] += a[i] * b[j];
        }
        __syncthreads();
    }

    #pragma unroll
    for (int i = 0; i < 8; i++) {
        float* Cp = C + (size_t)(bm + ty * 8 + i) * N + bn + tx * 8;
        *(float4*)(Cp)     = make_float4(acc[i][0], acc[i][1], acc[i][2], acc[i][3]);
        *(float4*)(Cp + 4) = make_float4(acc[i][4], acc[i][5], acc[i][6], acc[i][7]);
    }
}

// ---------------------------------------------------------------------------
// RoPE in-place on q,k parts of qkv. Interleaved pairs (even/odd).
// Angle computed in double (robust vs fast-math range reduction), then
// reduced to [0, 2pi) so sincosf is accurate.
// ---------------------------------------------------------------------------
__global__ void rope_kernel(float* __restrict__ qkv)
{
    int idx = blockIdx.x * blockDim.x + threadIdx.x;
    int i    =  idx        & 63;    // pair index 0..63
    int h    = (idx >> 6)  & 15;
    int part = (idx >> 10) & 1;     // 0 = q, 1 = k
    int l    = (idx >> 11) & 2047;
    int b    =  idx >> 22;          // 0..3

    const double LN1E4_OVER_64 = 0.14391156831212787;   // ln(10000)/64
    double invf = exp(-(double)i * LN1E4_OVER_64);
    double ang  = (double)l * invf;
    const double TWO_PI = 6.283185307179586476925286766559;
    ang -= TWO_PI * floor(ang / TWO_PI);

    float s, c;
    sincosf((float)ang, &s, &c);

    size_t base = ((size_t)(b * L_ + l)) * E3_ + (size_t)part * D_ + h * HD_ + 2 * i;
    float x1 = qkv[base];
    float x2 = qkv[base + 1];
    qkv[base]     = x1 * c - x2 * s;
    qkv[base + 1] = x2 * c + x1 * s;
}

// ---------------------------------------------------------------------------
// Flash attention, fp32, causal. 64 q-rows x 64 k-cols tiles, HD=128.
// 256 threads: thread (tr,tc) owns S rows tr*4..tr*4+3, S cols tc+16*jj,
// O cols tc+16*cc (conflict-free smem with stride 129 / 65).
// ---------------------------------------------------------------------------
#define FBM 64
#define FBN 64
#define QST 129
#define SST 65

__global__ __launch_bounds__(256) void flash_attn(const float* __restrict__ qkv,
                                                  float* __restrict__ y)
{
    extern __shared__ float sm[];
    float* Qs   = sm;                    // 64*129
    float* Ks   = Qs + FBM * QST;        // 64*129
    float* Vs   = Ks + FBN * QST;        // 64*129
    float* Ss   = Vs + FBN * QST;        // 64*65
    float* mrow = Ss + FBM * SST;        // 64
    float* lrow = mrow + FBM;            // 64
    float* arow = lrow + FBM;            // 64

    const int bh = blockIdx.y;
    const int b  = bh >> 4;
    const int h  = bh & 15;
    const int q0 = blockIdx.x * FBM;
    const int tid = threadIdx.x;
    const int tc  = tid & 15;
    const int tr  = tid >> 4;
    const int r0  = tr * 4;

    const float* qb = qkv + (size_t)b * L_ * E3_ + (size_t)h * HD_;
    const float* kb = qb + D_;
    const float* vb = qb + 2 * D_;

    for (int i = tid; i < FBM * HD_; i += 256) {
        int r = i >> 7, c = i & 127;
        Qs[r * QST + c] = qb[(size_t)(q0 + r) * E3_ + c];
    }
    if (tid < FBM) { mrow[tid] = -1e30f; lrow[tid] = 0.f; }

    float acc[4][8];
    #pragma unroll
    for (int rr = 0; rr < 4; rr++)
        #pragma unroll
        for (int cc = 0; cc < 8; cc++) acc[rr][cc] = 0.f;

    const float scale = 0.08838834764831845f;  // 1/sqrt(128)

    for (int k0 = 0; k0 <= q0; k0 += FBN) {
        __syncthreads();   // Q ready (first iter) / previous PV done
        for (int i = tid; i < FBN * HD_; i += 256) {
            int r = i >> 7, c = i & 127;
            size_t g = (size_t)(k0 + r) * E3_ + c;
            Ks[r * QST + c] = kb[g];
            Vs[r * QST + c] = vb[g];
        }
        __syncthreads();

        // S = Q K^T
        float s[4][4] = {{0.f}};
        for (int k = 0; k < HD_; k++) {
            float qv[4], kv[4];
            #pragma unroll
            for (int rr = 0; rr < 4; rr++) qv[rr] = Qs[(r0 + rr) * QST + k];
            #pragma unroll
            for (int jj = 0; jj < 4; jj++) kv[jj] = Ks[(tc + 16 * jj) * QST + k];
            #pragma unroll
            for (int rr = 0; rr < 4; rr++)
                #pragma unroll
                for (int jj = 0; jj < 4; jj++)
                    s[rr][jj] += qv[rr] * kv[jj];
        }

        const bool diag = (k0 == q0);
        #pragma unroll
        for (int rr = 0; rr < 4; rr++)
            #pragma unroll
            for (int jj = 0; jj < 4; jj++) {
                int j = tc + 16 * jj;
                float v = s[rr][jj] * scale;
                if (diag && j > r0 + rr) v = -1e30f;
                Ss[(r0 + rr) * SST + j] = v;
            }
        __syncthreads();

        // online softmax, one thread per row
        if (tid < FBM) {
            int r = tid;
            float mo = mrow[r];
            float mt = mo;
            for (int j = 0; j < FBN; j++) mt = fmaxf(mt, Ss[r * SST + j]);
            float al  = __expf(mo - mt);
            float sum = 0.f;
            for (int j = 0; j < FBN; j++) {
                float p = __expf(Ss[r * SST + j] - mt);
                Ss[r * SST + j] = p;
                sum += p;
            }
            lrow[r] = lrow[r] * al + sum;
            mrow[r] = mt;
            arow[r] = al;
        }
        __syncthreads();

        // rescale accumulators, then O += P @ V
        #pragma unroll
        for (int rr = 0; rr < 4; rr++) {
            float a = arow[r0 + rr];
            #pragma unroll
            for (int cc = 0; cc < 8; cc++) acc[rr][cc] *= a;
        }
        for (int j = 0; j < FBN; j++) {
            float p[4];
            #pragma unroll
            for (int rr = 0; rr < 4; rr++) p[rr] = Ss[(r0 + rr) * SST + j];
            #pragma unroll
            for (int cc = 0; cc < 8; cc++) {
                float v = Vs[j * QST + tc + 16 * cc];
                #pragma unroll
                for (int rr = 0; rr < 4; rr++) acc[rr][cc] += p[rr] * v;
            }
        }
    }

    // write y[b, q0+r, h*128 + c]
    #pragma unroll
    for (int rr = 0; rr < 4; rr++) {
        float inv = 1.f / lrow[r0 + rr];
        size_t orow = ((size_t)(b * L_ + q0 + r0 + rr)) * D_ + h * HD_;
        #pragma unroll
        for (int cc = 0; cc < 8; cc++)
            y[orow + tc + 16 * cc] = acc[rr][cc] * inv;
    }
}

// ---------------------------------------------------------------------------
extern "C" void kernel_launch(void* const* d_in, const int* in_sizes, int n_in,
                              void* d_out, int out_size)
{
    const float* x     = (const float*)d_in[0];   // [B,L,D]
    const float* w_qkv = (const float*)d_in[1];   // [3D,D]
    const float* w_o   = (const float*)d_in[2];   // [D,D]
    float* out = (float*)d_out;                   // [B,L,D]

    float *qkv, *y;
    cudaGetSymbolAddress((void**)&qkv, g_qkv);
    cudaGetSymbolAddress((void**)&y,   g_y);

    // 1) qkv = x @ w_qkv^T     (M=8192, N=6144, K=2048)
    sgemm_nt<<<dim3(E3_ / 128, M_ / 128), 256>>>(x, w_qkv, qkv, M_, E3_, D_);

    // 2) RoPE in-place on q,k parts
    rope_kernel<<<(B_ * L_ * 2 * H_ * 64) / 256, 256>>>(qkv);

    // 3) causal flash attention -> y [B,L,D]
    const int FLASH_SMEM = (3 * FBM * QST + FBM * SST + 3 * FBM) * (int)sizeof(float);
    cudaFuncSetAttribute(flash_attn, cudaFuncAttributeMaxDynamicSharedMemorySize, FLASH_SMEM);
    flash_attn<<<dim3(L_ / FBM, B_ * H_), 256, FLASH_SMEM>>>(qkv, y);

    // 4) out = y @ w_o^T       (M=8192, N=2048, K=2048)
    sgemm_nt<<<dim3(D_ / 128, M_ / 128), 256>>>(y, w_o, out, M_, D_, D_);
}

// round 3
// speedup vs baseline: 1.7935x; 1.7935x over previous
#include <cuda_runtime.h>
#include <cuda_bf16.h>
#include <math.h>
#include <stdint.h>

#define B_  4
#define L_  2048
#define D_  2048
#define H_  16
#define HD_ 128
#define M_  (B_ * L_)   // 8192
#define E3_ (3 * D_)    // 6144

// ---------------- scratch (allocation-free rule) ----------------
__device__ float g_qkv[(size_t)M_ * E3_];
__device__ float g_y[(size_t)M_ * D_];
__device__ __nv_bfloat16 g_xh[(size_t)M_ * D_], g_xl[(size_t)M_ * D_];
__device__ __nv_bfloat16 g_wqh[(size_t)E3_ * D_], g_wql[(size_t)E3_ * D_];
__device__ __nv_bfloat16 g_woh[(size_t)D_ * D_], g_wol[(size_t)D_ * D_];
__device__ __nv_bfloat16 g_yh[(size_t)M_ * D_], g_yl[(size_t)M_ * D_];

// ---------------- helpers ----------------
__device__ __forceinline__ uint32_t smem_u32(const void* p) {
    uint32_t a;
    asm("{ .reg .u64 t; cvta.to.shared.u64 t, %1; cvt.u32.u64 %0, t; }" : "=r"(a) : "l"(p));
    return a;
}
#define CP16(dst, src)  asm volatile("cp.async.cg.shared.global [%0], [%1], 16;" :: "r"(dst), "l"(src) : "memory")
#define CP_COMMIT()     asm volatile("cp.async.commit_group;" ::: "memory")
#define SWZ(o) ((o) ^ (((o) >> 3) & 0x70))

#define LDSM4(r0, r1, r2, r3, addr) \
    asm volatile("ldmatrix.sync.aligned.m8n8.x4.shared.b16 {%0,%1,%2,%3}, [%4];" \
        : "=r"(r0), "=r"(r1), "=r"(r2), "=r"(r3) : "r"(addr))

__device__ __forceinline__ void mma_bf16(float* c, const uint32_t* a, const uint32_t* b) {
    asm volatile(
        "mma.sync.aligned.m16n8k16.row.col.f32.bf16.bf16.f32 "
        "{%0,%1,%2,%3}, {%4,%5,%6,%7}, {%8,%9}, {%0,%1,%2,%3};"
        : "+f"(c[0]), "+f"(c[1]), "+f"(c[2]), "+f"(c[3])
        : "r"(a[0]), "r"(a[1]), "r"(a[2]), "r"(a[3]), "r"(b[0]), "r"(b[1]));
}

// ---------------- fp32 -> bf16 hi/lo split ----------------
__global__ void split_bf16(const float* __restrict__ x,
                           __nv_bfloat16* __restrict__ hi,
                           __nv_bfloat16* __restrict__ lo, int n4)
{
    int i = blockIdx.x * blockDim.x + threadIdx.x;
    if (i >= n4) return;
    float4 v = ((const float4*)x)[i];
    float f[4] = {v.x, v.y, v.z, v.w};
    __nv_bfloat162 h2[2], l2[2];
    #pragma unroll
    for (int j = 0; j < 4; j++) {
        __nv_bfloat16 h = __float2bfloat16(f[j]);
        __nv_bfloat16 l = __float2bfloat16(f[j] - __bfloat162float(h));
        if (j & 1) { h2[j >> 1].y = h; l2[j >> 1].y = l; }
        else       { h2[j >> 1].x = h; l2[j >> 1].x = l; }
    }
    ((__nv_bfloat162*)hi)[2 * i]     = h2[0];
    ((__nv_bfloat162*)hi)[2 * i + 1] = h2[1];
    ((__nv_bfloat162*)lo)[2 * i]     = l2[0];
    ((__nv_bfloat162*)lo)[2 * i + 1] = l2[1];
}

// ---------------------------------------------------------------------------
// bf16x3 GEMM via mma.sync: C[M,N] = A[M,K] * B[N,K]^T
// CTA 128x128, BK=64, 8 warps (4M x 2N, warp tile 32x64), 2-stage cp.async.
// SMEM tiles SW128-swizzled, ldmatrix x4 loads, fp32 accum in registers.
// ---------------------------------------------------------------------------
#define BM 128
#define BN 128
#define BK 64
#define STAGE_BYTES 65536      // Ah 16K | Al 16K | Bh 16K | Bl 16K
#define GEMM_SMEM (2 * STAGE_BYTES)

__global__ __launch_bounds__(256, 1) void gemm_bf16x3(
    const __nv_bfloat16* __restrict__ Ah, const __nv_bfloat16* __restrict__ Al,
    const __nv_bfloat16* __restrict__ Bh, const __nv_bfloat16* __restrict__ Bl,
    float* __restrict__ C, int M, int N, int K)
{
    extern __shared__ char smem[];
    const uint32_t sb = smem_u32(smem);
    const int tid  = threadIdx.x;
    const int wid  = tid >> 5;
    const int lane = tid & 31;
    const int wm = wid >> 1;        // 0..3  (M)
    const int wn = wid & 1;         // 0..1  (N)
    const int bm = blockIdx.y * BM;
    const int bn = blockIdx.x * BN;
    const int NC = K / BK;

    const __nv_bfloat16* gA[2] = {Ah + (size_t)bm * K, Al + (size_t)bm * K};
    const __nv_bfloat16* gB[2] = {Bh + (size_t)bn * K, Bl + (size_t)bn * K};

    // per-thread load coords: 4 iterations x (row, 16B chunk) per tile
    const int lr0 = tid >> 3;       // +32*it rows
    const int lc  = tid & 7;        // 16B chunk (8 bf16)

    auto load_chunk = [&](int ic, int s) {
        const uint32_t st = sb + s * STAGE_BYTES;
        const size_t k0 = (size_t)ic * BK;
        #pragma unroll
        for (int it = 0; it < 4; it++) {
            int r = lr0 + it * 32;
            uint32_t off = SWZ((uint32_t)(r * 128 + lc * 16));
            size_t g = (size_t)r * K + k0 + lc * 8;
            CP16(st + off,         gA[0] + g);
            CP16(st + 16384 + off, gA[1] + g);
            CP16(st + 32768 + off, gB[0] + g);
            CP16(st + 49152 + off, gB[1] + g);
        }
        CP_COMMIT();
    };

    float acc[2][8][4];
    #pragma unroll
    for (int m = 0; m < 2; m++)
        #pragma unroll
        for (int n = 0; n < 8; n++)
            #pragma unroll
            for (int v = 0; v < 4; v++) acc[m][n][v] = 0.f;

    load_chunk(0, 0);
    if (NC > 1) load_chunk(1, 1);

    // precomputed intra-tile ldmatrix byte offsets (depend only on lane)
    const int a_row = wm * 32 + (lane & 15);
    const int a_kb  = (lane >> 4) << 4;              // 0 or 16 bytes (k+8)
    const int b_row = wn * 64 + (lane & 7) + ((lane >> 4) << 3);
    const int b_kb  = ((lane >> 3) & 1) << 4;

    for (int ic = 0; ic < NC; ic++) {
        const int s = ic & 1;
        if (ic == NC - 1) asm volatile("cp.async.wait_group 0;" ::: "memory");
        else              asm volatile("cp.async.wait_group 1;" ::: "memory");
        __syncthreads();

        const uint32_t st = sb + s * STAGE_BYTES;

        #pragma unroll
        for (int ks = 0; ks < 4; ks++) {
            uint32_t a[2][2][4];   // [split][mtile][reg]
            uint32_t b[2][8][2];   // [split][ntile][reg]
            #pragma unroll
            for (int m = 0; m < 2; m++) {
                uint32_t off = SWZ((uint32_t)((a_row + m * 16) * 128 + ks * 32 + a_kb));
                LDSM4(a[0][m][0], a[0][m][1], a[0][m][2], a[0][m][3], st + off);
                LDSM4(a[1][m][0], a[1][m][1], a[1][m][2], a[1][m][3], st + 16384 + off);
            }
            #pragma unroll
            for (int p = 0; p < 4; p++) {
                uint32_t off = SWZ((uint32_t)((b_row + p * 16) * 128 + ks * 32 + b_kb));
                LDSM4(b[0][2*p][0], b[0][2*p][1], b[0][2*p+1][0], b[0][2*p+1][1], st + 32768 + off);
                LDSM4(b[1][2*p][0], b[1][2*p][1], b[1][2*p+1][0], b[1][2*p+1][1], st + 49152 + off);
            }
            #pragma unroll
            for (int m = 0; m < 2; m++)
                #pragma unroll
                for (int n = 0; n < 8; n++) {
                    mma_bf16(acc[m][n], a[0][m], b[0][n]);  // Ah*Bh
                    mma_bf16(acc[m][n], a[0][m], b[1][n]);  // Ah*Bl
                    mma_bf16(acc[m][n], a[1][m], b[0][n]);  // Al*Bh
                }
        }
        __syncthreads();
        if (ic + 2 < NC) load_chunk(ic + 2, s);
    }

    // epilogue: c-frag m16n8: (r=lane/4, c=2*(lane%4)) and (r+8, c)
    const int er = lane >> 2;
    const int ec = (lane & 3) * 2;
    #pragma unroll
    for (int m = 0; m < 2; m++) {
        int row0 = bm + wm * 32 + m * 16 + er;
        #pragma unroll
        for (int n = 0; n < 8; n++) {
            int col = bn + wn * 64 + n * 8 + ec;
            *(float2*)(C + (size_t)row0 * N + col)       = make_float2(acc[m][n][0], acc[m][n][1]);
            *(float2*)(C + (size_t)(row0 + 8) * N + col) = make_float2(acc[m][n][2], acc[m][n][3]);
        }
    }
}

// ---------------- RoPE (unchanged, known-good) ----------------
__global__ void rope_kernel(float* __restrict__ qkv)
{
    int idx = blockIdx.x * blockDim.x + threadIdx.x;
    int i    =  idx        & 63;
    int h    = (idx >> 6)  & 15;
    int part = (idx >> 10) & 1;
    int l    = (idx >> 11) & 2047;
    int b    =  idx >> 22;

    const double LN1E4_OVER_64 = 0.14391156831212787;
    double invf = exp(-(double)i * LN1E4_OVER_64);
    double ang  = (double)l * invf;
    const double TWO_PI = 6.283185307179586476925286766559;
    ang -= TWO_PI * floor(ang / TWO_PI);

    float s, c;
    sincosf((float)ang, &s, &c);

    size_t base = ((size_t)(b * L_ + l)) * E3_ + (size_t)part * D_ + h * HD_ + 2 * i;
    float x1 = qkv[base];
    float x2 = qkv[base + 1];
    qkv[base]     = x1 * c - x2 * s;
    qkv[base + 1] = x2 * c + x1 * s;
}

// ---------------- fp32 flash attention (unchanged, known-good) ----------------
#define FBM 64
#define FBN 64
#define QST 129
#define SST 65

__global__ __launch_bounds__(256) void flash_attn(const float* __restrict__ qkv,
                                                  float* __restrict__ y)
{
    extern __shared__ float sm[];
    float* Qs   = sm;
    float* Ks   = Qs + FBM * QST;
    float* Vs   = Ks + FBN * QST;
    float* Ss   = Vs + FBN * QST;
    float* mrow = Ss + FBM * SST;
    float* lrow = mrow + FBM;
    float* arow = lrow + FBM;

    const int bh = blockIdx.y;
    const int b  = bh >> 4;
    const int h  = bh & 15;
    const int q0 = blockIdx.x * FBM;
    const int tid = threadIdx.x;
    const int tc  = tid & 15;
    const int tr  = tid >> 4;
    const int r0  = tr * 4;

    const float* qb = qkv + (size_t)b * L_ * E3_ + (size_t)h * HD_;
    const float* kb = qb + D_;
    const float* vb = qb + 2 * D_;

    for (int i = tid; i < FBM * HD_; i += 256) {
        int r = i >> 7, c = i & 127;
        Qs[r * QST + c] = qb[(size_t)(q0 + r) * E3_ + c];
    }
    if (tid < FBM) { mrow[tid] = -1e30f; lrow[tid] = 0.f; }

    float acc[4][8];
    #pragma unroll
    for (int rr = 0; rr < 4; rr++)
        #pragma unroll
        for (int cc = 0; cc < 8; cc++) acc[rr][cc] = 0.f;

    const float scale = 0.08838834764831845f;

    for (int k0 = 0; k0 <= q0; k0 += FBN) {
        __syncthreads();
        for (int i = tid; i < FBN * HD_; i += 256) {
            int r = i >> 7, c = i & 127;
            size_t g = (size_t)(k0 + r) * E3_ + c;
            Ks[r * QST + c] = kb[g];
            Vs[r * QST + c] = vb[g];
        }
        __syncthreads();

        float s[4][4] = {{0.f}};
        for (int k = 0; k < HD_; k++) {
            float qv[4], kv[4];
            #pragma unroll
            for (int rr = 0; rr < 4; rr++) qv[rr] = Qs[(r0 + rr) * QST + k];
            #pragma unroll
            for (int jj = 0; jj < 4; jj++) kv[jj] = Ks[(tc + 16 * jj) * QST + k];
            #pragma unroll
            for (int rr = 0; rr < 4; rr++)
                #pragma unroll
                for (int jj = 0; jj < 4; jj++)
                    s[rr][jj] += qv[rr] * kv[jj];
        }

        const bool diag = (k0 == q0);
        #pragma unroll
        for (int rr = 0; rr < 4; rr++)
            #pragma unroll
            for (int jj = 0; jj < 4; jj++) {
                int j = tc + 16 * jj;
                float v = s[rr][jj] * scale;
                if (diag && j > r0 + rr) v = -1e30f;
                Ss[(r0 + rr) * SST + j] = v;
            }
        __syncthreads();

        if (tid < FBM) {
            int r = tid;
            float mo = mrow[r];
            float mt = mo;
            for (int j = 0; j < FBN; j++) mt = fmaxf(mt, Ss[r * SST + j]);
            float al  = __expf(mo - mt);
            float sum = 0.f;
            for (int j = 0; j < FBN; j++) {
                float p = __expf(Ss[r * SST + j] - mt);
                Ss[r * SST + j] = p;
                sum += p;
            }
            lrow[r] = lrow[r] * al + sum;
            mrow[r] = mt;
            arow[r] = al;
        }
        __syncthreads();

        #pragma unroll
        for (int rr = 0; rr < 4; rr++) {
            float a = arow[r0 + rr];
            #pragma unroll
            for (int cc = 0; cc < 8; cc++) acc[rr][cc] *= a;
        }
        for (int j = 0; j < FBN; j++) {
            float p[4];
            #pragma unroll
            for (int rr = 0; rr < 4; rr++) p[rr] = Ss[(r0 + rr) * SST + j];
            #pragma unroll
            for (int cc = 0; cc < 8; cc++) {
                float v = Vs[j * QST + tc + 16 * cc];
                #pragma unroll
                for (int rr = 0; rr < 4; rr++) acc[rr][cc] += p[rr] * v;
            }
        }
    }

    #pragma unroll
    for (int rr = 0; rr < 4; rr++) {
        float inv = 1.f / lrow[r0 + rr];
        size_t orow = ((size_t)(b * L_ + q0 + r0 + rr)) * D_ + h * HD_;
        #pragma unroll
        for (int cc = 0; cc < 8; cc++)
            y[orow + tc + 16 * cc] = acc[rr][cc] * inv;
    }
}

// ---------------------------------------------------------------------------
extern "C" void kernel_launch(void* const* d_in, const int* in_sizes, int n_in,
                              void* d_out, int out_size)
{
    const float* x     = (const float*)d_in[0];
    const float* w_qkv = (const float*)d_in[1];
    const float* w_o   = (const float*)d_in[2];
    float* out = (float*)d_out;

    float *qkv, *y;
    __nv_bfloat16 *xh, *xl, *wqh, *wql, *woh, *wol, *yh, *yl;
    cudaGetSymbolAddress((void**)&qkv, g_qkv);
    cudaGetSymbolAddress((void**)&y,   g_y);
    cudaGetSymbolAddress((void**)&xh,  g_xh);  cudaGetSymbolAddress((void**)&xl, g_xl);
    cudaGetSymbolAddress((void**)&wqh, g_wqh); cudaGetSymbolAddress((void**)&wql, g_wql);
    cudaGetSymbolAddress((void**)&woh, g_woh); cudaGetSymbolAddress((void**)&wol, g_wol);
    cudaGetSymbolAddress((void**)&yh,  g_yh);  cudaGetSymbolAddress((void**)&yl, g_yl);

    cudaFuncSetAttribute(gemm_bf16x3, cudaFuncAttributeMaxDynamicSharedMemorySize, GEMM_SMEM);

    // split inputs to bf16 hi/lo
    split_bf16<<<(M_ * D_ / 4) / 256, 256>>>(x, xh, xl, M_ * D_ / 4);
    split_bf16<<<(E3_ * D_ / 4) / 256, 256>>>(w_qkv, wqh, wql, E3_ * D_ / 4);
    split_bf16<<<(D_ * D_ / 4) / 256, 256>>>(w_o, woh, wol, D_ * D_ / 4);

    // 1) qkv = x @ w_qkv^T  (HMMA bf16x3)
    gemm_bf16x3<<<dim3(E3_ / BN, M_ / BM), 256, GEMM_SMEM>>>(xh, xl, wqh, wql, qkv, M_, E3_, D_);

    // 2) RoPE in-place
    rope_kernel<<<(B_ * L_ * 2 * H_ * 64) / 256, 256>>>(qkv);

    // 3) causal flash attention (fp32)
    const int FLASH_SMEM = (3 * FBM * QST + FBM * SST + 3 * FBM) * (int)sizeof(float);
    cudaFuncSetAttribute(flash_attn, cudaFuncAttributeMaxDynamicSharedMemorySize, FLASH_SMEM);
    flash_attn<<<dim3(L_ / FBM, B_ * H_), 256, FLASH_SMEM>>>(qkv, y);

    // 4) out = y @ w_o^T  (HMMA bf16x3)
    split_bf16<<<(M_ * D_ / 4) / 256, 256>>>(y, yh, yl, M_ * D_ / 4);
    gemm_bf16x3<<<dim3(D_ / BN, M_ / BM), 256, GEMM_SMEM>>>(yh, yl, woh, wol, out, M_, D_, D_);
}

// round 4
// speedup vs baseline: 4.2201x; 2.3531x over previous
#include <cuda_runtime.h>
#include <cuda_bf16.h>
#include <math.h>
#include <stdint.h>

#define B_  4
#define L_  2048
#define D_  2048
#define H_  16
#define HD_ 128
#define M_  (B_ * L_)   // 8192
#define E3_ (3 * D_)    // 6144

// ---------------- scratch (allocation-free rule) ----------------
__device__ float g_qkv[(size_t)M_ * E3_];
__device__ __nv_bfloat16 g_xh[(size_t)M_ * D_], g_xl[(size_t)M_ * D_];
__device__ __nv_bfloat16 g_wqh[(size_t)E3_ * D_], g_wql[(size_t)E3_ * D_];
__device__ __nv_bfloat16 g_woh[(size_t)D_ * D_], g_wol[(size_t)D_ * D_];
__device__ __nv_bfloat16 g_yh[(size_t)M_ * D_], g_yl[(size_t)M_ * D_];
__device__ __nv_bfloat16 g_qh[(size_t)M_ * D_], g_ql[(size_t)M_ * D_];
__device__ __nv_bfloat16 g_kh[(size_t)M_ * D_], g_kl[(size_t)M_ * D_];
__device__ __nv_bfloat16 g_vth[(size_t)M_ * D_], g_vtl[(size_t)M_ * D_];
__device__ float g_cos[L_ * 64], g_sin[L_ * 64];

// ---------------- helpers ----------------
__device__ __forceinline__ uint32_t smem_u32(const void* p) {
    uint32_t a;
    asm("{ .reg .u64 t; cvta.to.shared.u64 t, %1; cvt.u32.u64 %0, t; }" : "=r"(a) : "l"(p));
    return a;
}
#define CP16(dst, src)  asm volatile("cp.async.cg.shared.global [%0], [%1], 16;" :: "r"(dst), "l"(src) : "memory")
#define CP_COMMIT()     asm volatile("cp.async.commit_group;" ::: "memory")
#define CP_WAIT0()      asm volatile("cp.async.wait_group 0;" ::: "memory")
#define CP_WAIT1()      asm volatile("cp.async.wait_group 1;" ::: "memory")
#define CP_WAIT2()      asm volatile("cp.async.wait_group 2;" ::: "memory")
#define SWZ(o) ((o) ^ (((o) >> 3) & 0x70))

#define LDSM4(r0, r1, r2, r3, addr) \
    asm volatile("ldmatrix.sync.aligned.m8n8.x4.shared.b16 {%0,%1,%2,%3}, [%4];" \
        : "=r"(r0), "=r"(r1), "=r"(r2), "=r"(r3) : "r"(addr))

__device__ __forceinline__ void mma_bf16(float* c, const uint32_t* a, uint32_t b0, uint32_t b1) {
    asm volatile(
        "mma.sync.aligned.m16n8k16.row.col.f32.bf16.bf16.f32 "
        "{%0,%1,%2,%3}, {%4,%5,%6,%7}, {%8,%9}, {%0,%1,%2,%3};"
        : "+f"(c[0]), "+f"(c[1]), "+f"(c[2]), "+f"(c[3])
        : "r"(a[0]), "r"(a[1]), "r"(a[2]), "r"(a[3]), "r"(b0), "r"(b1));
}

__device__ __forceinline__ uint32_t pack_bf16(float a, float b) {
    __nv_bfloat162 t = __floats2bfloat162_rn(a, b);
    return *reinterpret_cast<uint32_t*>(&t);
}

// ---------------- fp32 -> bf16 hi/lo split ----------------
__global__ void split_bf16(const float* __restrict__ x,
                           __nv_bfloat16* __restrict__ hi,
                           __nv_bfloat16* __restrict__ lo, int n4)
{
    int i = blockIdx.x * blockDim.x + threadIdx.x;
    if (i >= n4) return;
    float4 v = ((const float4*)x)[i];
    float f[4] = {v.x, v.y, v.z, v.w};
    __nv_bfloat162 h2[2], l2[2];
    #pragma unroll
    for (int j = 0; j < 4; j++) {
        __nv_bfloat16 h = __float2bfloat16(f[j]);
        __nv_bfloat16 l = __float2bfloat16(f[j] - __bfloat162float(h));
        if (j & 1) { h2[j >> 1].y = h; l2[j >> 1].y = l; }
        else       { h2[j >> 1].x = h; l2[j >> 1].x = l; }
    }
    ((__nv_bfloat162*)hi)[2 * i]     = h2[0];
    ((__nv_bfloat162*)hi)[2 * i + 1] = h2[1];
    ((__nv_bfloat162*)lo)[2 * i]     = l2[0];
    ((__nv_bfloat162*)lo)[2 * i + 1] = l2[1];
}

// ---------------------------------------------------------------------------
// bf16x3 GEMM via mma.sync: C[M,N] = A[M,K] * B[N,K]^T
// CTA 128x128, BK=64, 8 warps (4Mx2N), 3-stage cp.async pipeline.
// ---------------------------------------------------------------------------
#define BM 128
#define BN 128
#define BK 64
#define STAGE_BYTES 65536
#define GEMM_SMEM (3 * STAGE_BYTES)

__global__ __launch_bounds__(256, 1) void gemm_bf16x3(
    const __nv_bfloat16* __restrict__ Ah, const __nv_bfloat16* __restrict__ Al,
    const __nv_bfloat16* __restrict__ Bh, const __nv_bfloat16* __restrict__ Bl,
    float* __restrict__ C, int M, int N, int K)
{
    extern __shared__ char smem[];
    const uint32_t sb = smem_u32(smem);
    const int tid  = threadIdx.x;
    const int wid  = tid >> 5;
    const int lane = tid & 31;
    const int wm = wid >> 1;
    const int wn = wid & 1;
    const int bm = blockIdx.y * BM;
    const int bn = blockIdx.x * BN;
    const int NC = K / BK;

    const __nv_bfloat16* gA[2] = {Ah + (size_t)bm * K, Al + (size_t)bm * K};
    const __nv_bfloat16* gB[2] = {Bh + (size_t)bn * K, Bl + (size_t)bn * K};

    const int lr0 = tid >> 3;
    const int lc  = tid & 7;

    auto load_chunk = [&](int ic, int s) {
        const uint32_t st = sb + s * STAGE_BYTES;
        const size_t k0 = (size_t)ic * BK;
        #pragma unroll
        for (int it = 0; it < 4; it++) {
            int r = lr0 + it * 32;
            uint32_t off = SWZ((uint32_t)(r * 128 + lc * 16));
            size_t g = (size_t)r * K + k0 + lc * 8;
            CP16(st + off,         gA[0] + g);
            CP16(st + 16384 + off, gA[1] + g);
            CP16(st + 32768 + off, gB[0] + g);
            CP16(st + 49152 + off, gB[1] + g);
        }
        CP_COMMIT();
    };

    float acc[2][8][4];
    #pragma unroll
    for (int m = 0; m < 2; m++)
        #pragma unroll
        for (int n = 0; n < 8; n++)
            #pragma unroll
            for (int v = 0; v < 4; v++) acc[m][n][v] = 0.f;

    load_chunk(0, 0);
    load_chunk(1, 1);
    load_chunk(2, 2);

    const int a_row = wm * 32 + (lane & 15);
    const int a_kb  = (lane >> 4) << 4;
    const int b_row = wn * 64 + (lane & 7) + ((lane >> 4) << 3);
    const int b_kb  = ((lane >> 3) & 1) << 4;

    for (int ic = 0; ic < NC; ic++) {
        const int s = ic % 3;
        const int rem = NC - 1 - ic;
        if (rem == 0) CP_WAIT0();
        else if (rem == 1) CP_WAIT1();
        else CP_WAIT2();
        __syncthreads();

        const uint32_t st = sb + s * STAGE_BYTES;

        #pragma unroll
        for (int ks = 0; ks < 4; ks++) {
            uint32_t a[2][2][4];
            uint32_t b[2][8][2];
            #pragma unroll
            for (int m = 0; m < 2; m++) {
                uint32_t off = SWZ((uint32_t)((a_row + m * 16) * 128 + ks * 32 + a_kb));
                LDSM4(a[0][m][0], a[0][m][1], a[0][m][2], a[0][m][3], st + off);
                LDSM4(a[1][m][0], a[1][m][1], a[1][m][2], a[1][m][3], st + 16384 + off);
            }
            #pragma unroll
            for (int p = 0; p < 4; p++) {
                uint32_t off = SWZ((uint32_t)((b_row + p * 16) * 128 + ks * 32 + b_kb));
                LDSM4(b[0][2*p][0], b[0][2*p][1], b[0][2*p+1][0], b[0][2*p+1][1], st + 32768 + off);
                LDSM4(b[1][2*p][0], b[1][2*p][1], b[1][2*p+1][0], b[1][2*p+1][1], st + 49152 + off);
            }
            #pragma unroll
            for (int m = 0; m < 2; m++)
                #pragma unroll
                for (int n = 0; n < 8; n++) {
                    mma_bf16(acc[m][n], a[0][m], b[0][n][0], b[0][n][1]);
                    mma_bf16(acc[m][n], a[0][m], b[1][n][0], b[1][n][1]);
                    mma_bf16(acc[m][n], a[1][m], b[0][n][0], b[0][n][1]);
                }
        }
        __syncthreads();
        if (ic + 3 < NC) load_chunk(ic + 3, s);
    }

    const int er = lane >> 2;
    const int ec = (lane & 3) * 2;
    #pragma unroll
    for (int m = 0; m < 2; m++) {
        int row0 = bm + wm * 32 + m * 16 + er;
        #pragma unroll
        for (int n = 0; n < 8; n++) {
            int col = bn + wn * 64 + n * 8 + ec;
            *(float2*)(C + (size_t)row0 * N + col)       = make_float2(acc[m][n][0], acc[m][n][1]);
            *(float2*)(C + (size_t)(row0 + 8) * N + col) = make_float2(acc[m][n][2], acc[m][n][3]);
        }
    }
}

// ---------------- cos/sin table (matches R1 double-precision math) ----------------
__global__ void rope_table(float* __restrict__ ct, float* __restrict__ st)
{
    int idx = blockIdx.x * blockDim.x + threadIdx.x;
    if (idx >= L_ * 64) return;
    int l = idx >> 6, i = idx & 63;
    const double LN1E4_OVER_64 = 0.14391156831212787;
    double invf = exp(-(double)i * LN1E4_OVER_64);
    double ang  = (double)l * invf;
    const double TWO_PI = 6.283185307179586476925286766559;
    ang -= TWO_PI * floor(ang / TWO_PI);
    float s, c;
    sincosf((float)ang, &s, &c);
    ct[idx] = c; st[idx] = s;
}

// ---------------------------------------------------------------------------
// Fused RoPE + bf16 hi/lo split + relayout:
//   qkv fp32 [b,l,6144] -> qh/ql, kh/kl [b,h,l,128] ; vth/vtl [b,h,128,l]
// One block per (b,h, 32-l tile), 256 threads.
// ---------------------------------------------------------------------------
__global__ __launch_bounds__(256) void qkv_split(
    const float* __restrict__ qkv,
    const float* __restrict__ ct, const float* __restrict__ st,
    __nv_bfloat16* __restrict__ qh, __nv_bfloat16* __restrict__ ql,
    __nv_bfloat16* __restrict__ kh, __nv_bfloat16* __restrict__ kl,
    __nv_bfloat16* __restrict__ vth, __nv_bfloat16* __restrict__ vtl)
{
    __shared__ float vtile[32][129];
    const int bh = blockIdx.y;
    const int b = bh >> 4, h = bh & 15;
    const int l0 = blockIdx.x * 32;
    const int tid = threadIdx.x;
    const int lane = tid & 31;
    const int hd0 = lane * 4;

    #pragma unroll
    for (int pass = 0; pass < 4; pass++) {
        int ll = (tid >> 5) + pass * 8;
        int l  = l0 + ll;
        size_t rowbase = (size_t)(b * L_ + l) * E3_ + h * HD_ + hd0;
        int i0 = hd0 >> 1;
        float c0 = ct[l * 64 + i0],     s0 = st[l * 64 + i0];
        float c1 = ct[l * 64 + i0 + 1], s1 = st[l * 64 + i0 + 1];

        // q
        float4 fq = *(const float4*)(qkv + rowbase);
        float q0 = fq.x * c0 - fq.y * s0, q1 = fq.y * c0 + fq.x * s0;
        float q2 = fq.z * c1 - fq.w * s1, q3 = fq.w * c1 + fq.z * s1;
        size_t o = (size_t)(bh * L_ + l) * HD_ + hd0;
        {
            __nv_bfloat16 h0 = __float2bfloat16(q0), h1 = __float2bfloat16(q1);
            __nv_bfloat16 h2 = __float2bfloat16(q2), h3 = __float2bfloat16(q3);
            *(__nv_bfloat162*)(qh + o)     = __nv_bfloat162(h0, h1);
            *(__nv_bfloat162*)(qh + o + 2) = __nv_bfloat162(h2, h3);
            *(__nv_bfloat162*)(ql + o)     = __floats2bfloat162_rn(q0 - __bfloat162float(h0), q1 - __bfloat162float(h1));
            *(__nv_bfloat162*)(ql + o + 2) = __floats2bfloat162_rn(q2 - __bfloat162float(h2), q3 - __bfloat162float(h3));
        }
        // k
        float4 fk = *(const float4*)(qkv + rowbase + D_);
        float k0v = fk.x * c0 - fk.y * s0, k1v = fk.y * c0 + fk.x * s0;
        float k2v = fk.z * c1 - fk.w * s1, k3v = fk.w * c1 + fk.z * s1;
        {
            __nv_bfloat16 h0 = __float2bfloat16(k0v), h1 = __float2bfloat16(k1v);
            __nv_bfloat16 h2 = __float2bfloat16(k2v), h3 = __float2bfloat16(k3v);
            *(__nv_bfloat162*)(kh + o)     = __nv_bfloat162(h0, h1);
            *(__nv_bfloat162*)(kh + o + 2) = __nv_bfloat162(h2, h3);
            *(__nv_bfloat162*)(kl + o)     = __floats2bfloat162_rn(k0v - __bfloat162float(h0), k1v - __bfloat162float(h1));
            *(__nv_bfloat162*)(kl + o + 2) = __floats2bfloat162_rn(k2v - __bfloat162float(h2), k3v - __bfloat162float(h3));
        }
        // v -> smem for transpose
        float4 fv = *(const float4*)(qkv + rowbase + 2 * D_);
        vtile[ll][hd0] = fv.x; vtile[ll][hd0 + 1] = fv.y;
        vtile[ll][hd0 + 2] = fv.z; vtile[ll][hd0 + 3] = fv.w;
    }
    __syncthreads();

    // transposed V write: thread -> (hd row, half of 32 l)
    const int r = tid >> 1;
    const int lh = (tid & 1) * 16;
    size_t vbase = (size_t)(bh * HD_ + r) * L_ + l0 + lh;
    #pragma unroll
    for (int j = 0; j < 16; j += 2) {
        float f0 = vtile[lh + j][r], f1 = vtile[lh + j + 1][r];
        __nv_bfloat16 h0 = __float2bfloat16(f0), h1 = __float2bfloat16(f1);
        *(__nv_bfloat162*)(vth + vbase + j) = __nv_bfloat162(h0, h1);
        *(__nv_bfloat162*)(vtl + vbase + j) =
            __floats2bfloat162_rn(f0 - __bfloat162float(h0), f1 - __bfloat162float(h1));
    }
}

// ---------------------------------------------------------------------------
// Flash attention, bf16x3 mma.sync. CTA: 128 q-rows, 8 warps (16 rows each).
// K/V tiles 64-wide, 2-stage cp.async. Q kept in smem. Writes yh/yl splits.
// SMEM: Q 64KB | 2 stages x (K 32KB + Vt 32KB) = 192KB.
// ---------------------------------------------------------------------------
#define ATT_SMEM 196608

__global__ __launch_bounds__(256, 1) void flash_mma(
    const __nv_bfloat16* __restrict__ qh, const __nv_bfloat16* __restrict__ ql,
    const __nv_bfloat16* __restrict__ kh, const __nv_bfloat16* __restrict__ kl,
    const __nv_bfloat16* __restrict__ vth, const __nv_bfloat16* __restrict__ vtl,
    __nv_bfloat16* __restrict__ yh, __nv_bfloat16* __restrict__ yl)
{
    extern __shared__ char smem[];
    const uint32_t sb = smem_u32(smem);
    const int tid = threadIdx.x, wid = tid >> 5, lane = tid & 31;
    const int bh = blockIdx.y;
    const int b = bh >> 4, h = bh & 15;
    const int q0 = blockIdx.x * 128;
    const int NB = q0 / 64 + 2;

    const size_t qkbase = (size_t)bh * L_ * HD_;
    const size_t vbase  = (size_t)bh * HD_ * L_;

    // Q: [split][half][128 rows][128B]
    #pragma unroll
    for (int it = 0; it < 16; it++) {
        int idx = tid + 256 * it;
        int c = idx & 15, r = (idx >> 4) & 127, sp = idx >> 11;
        const __nv_bfloat16* src = (sp ? ql : qh) + qkbase + (size_t)(q0 + r) * 128 + c * 8;
        CP16(sb + sp * 32768 + (c >> 3) * 16384 + SWZ((uint32_t)(r * 128 + (c & 7) * 16)), src);
    }
    auto load_kv = [&](int kb, int s) {
        const uint32_t st0 = sb + 65536 + s * 65536;
        const int k0 = kb * 64;
        #pragma unroll
        for (int it = 0; it < 8; it++) {           // K: [sp][half][64][128B]
            int idx = tid + 256 * it;
            int c = idx & 15, r = (idx >> 4) & 63, sp = idx >> 10;
            const __nv_bfloat16* src = (sp ? kl : kh) + qkbase + (size_t)(k0 + r) * 128 + c * 8;
            CP16(st0 + sp * 16384 + (c >> 3) * 8192 + SWZ((uint32_t)(r * 128 + (c & 7) * 16)), src);
        }
        #pragma unroll
        for (int it = 0; it < 8; it++) {           // Vt: [sp][128 hd][128B]
            int idx = tid + 256 * it;
            int c = idx & 7, r = (idx >> 3) & 127, sp = idx >> 10;
            const __nv_bfloat16* src = (sp ? vtl : vth) + vbase + (size_t)r * L_ + k0 + c * 8;
            CP16(st0 + 32768 + sp * 16384 + SWZ((uint32_t)(r * 128 + c * 16)), src);
        }
        CP_COMMIT();
    };

    load_kv(0, 0);     // group 0 = Q + stage0
    load_kv(1, 1);     // group 1 = stage1

    float o[16][4];
    #pragma unroll
    for (int n = 0; n < 16; n++)
        #pragma unroll
        for (int v = 0; v < 4; v++) o[n][v] = 0.f;
    float m0 = -1e30f, m1 = -1e30f, l0 = 0.f, l1 = 0.f;

    const int a_row = wid * 16 + (lane & 15);
    const uint32_t a_kb = (lane >> 4) << 4;
    const int b_row = (lane & 7) + ((lane >> 4) << 3);
    const uint32_t b_kb = ((lane >> 3) & 1) << 4;
    const float scale = 0.08838834764831845f;
    const int row0 = q0 + wid * 16 + (lane >> 2);
    const int ec = (lane & 3) * 2;

    for (int kb = 0; kb < NB; kb++) {
        const int s = kb & 1;
        if (kb == NB - 1) CP_WAIT0(); else CP_WAIT1();
        __syncthreads();
        const uint32_t st0 = sb + 65536 + s * 65536;
        const int k0 = kb * 64;

        // ---- S = Q K^T (bf16x3) ----
        float sc[8][4];
        #pragma unroll
        for (int n = 0; n < 8; n++)
            #pragma unroll
            for (int v = 0; v < 4; v++) sc[n][v] = 0.f;

        #pragma unroll
        for (int half = 0; half < 2; half++)
            #pragma unroll
            for (int ks = 0; ks < 4; ks++) {
                uint32_t qo = sb + half * 16384 + SWZ((uint32_t)(a_row * 128 + ks * 32 + a_kb));
                uint32_t aH[4], aL[4];
                LDSM4(aH[0], aH[1], aH[2], aH[3], qo);
                LDSM4(aL[0], aL[1], aL[2], aL[3], qo + 32768);
                #pragma unroll
                for (int p = 0; p < 4; p++) {
                    uint32_t ko = st0 + half * 8192 + SWZ((uint32_t)((b_row + p * 16) * 128 + ks * 32 + b_kb));
                    uint32_t bH[4], bL[4];
                    LDSM4(bH[0], bH[1], bH[2], bH[3], ko);
                    LDSM4(bL[0], bL[1], bL[2], bL[3], ko + 16384);
                    mma_bf16(sc[2*p],   aH, bH[0], bH[1]);
                    mma_bf16(sc[2*p],   aH, bL[0], bL[1]);
                    mma_bf16(sc[2*p],   aL, bH[0], bH[1]);
                    mma_bf16(sc[2*p+1], aH, bH[2], bH[3]);
                    mma_bf16(sc[2*p+1], aH, bL[2], bL[3]);
                    mma_bf16(sc[2*p+1], aL, bH[2], bH[3]);
                }
            }

        // ---- scale + causal mask ----
        const bool need_mask = (kb >= NB - 2);
        #pragma unroll
        for (int n = 0; n < 8; n++)
            #pragma unroll
            for (int v = 0; v < 4; v++) {
                float val = sc[n][v] * scale;
                if (need_mask) {
                    int col = k0 + n * 8 + ec + (v & 1);
                    int row = row0 + ((v >= 2) ? 8 : 0);
                    if (col > row) val = -1e30f;
                }
                sc[n][v] = val;
            }

        // ---- online softmax (rows owned per-warp; quad reduce) ----
        float mx0 = -1e30f, mx1 = -1e30f;
        #pragma unroll
        for (int n = 0; n < 8; n++) {
            mx0 = fmaxf(mx0, fmaxf(sc[n][0], sc[n][1]));
            mx1 = fmaxf(mx1, fmaxf(sc[n][2], sc[n][3]));
        }
        mx0 = fmaxf(mx0, __shfl_xor_sync(0xffffffffu, mx0, 1));
        mx0 = fmaxf(mx0, __shfl_xor_sync(0xffffffffu, mx0, 2));
        mx1 = fmaxf(mx1, __shfl_xor_sync(0xffffffffu, mx1, 1));
        mx1 = fmaxf(mx1, __shfl_xor_sync(0xffffffffu, mx1, 2));
        float nm0 = fmaxf(m0, mx0), nm1 = fmaxf(m1, mx1);
        float al0 = __expf(m0 - nm0), al1 = __expf(m1 - nm1);
        m0 = nm0; m1 = nm1;
        float ps0 = 0.f, ps1 = 0.f;
        #pragma unroll
        for (int n = 0; n < 8; n++) {
            float p0 = __expf(sc[n][0] - m0), p1 = __expf(sc[n][1] - m0);
            float p2 = __expf(sc[n][2] - m1), p3 = __expf(sc[n][3] - m1);
            sc[n][0] = p0; sc[n][1] = p1; sc[n][2] = p2; sc[n][3] = p3;
            ps0 += p0 + p1; ps1 += p2 + p3;
        }
        l0 = l0 * al0 + ps0;
        l1 = l1 * al1 + ps1;
        #pragma unroll
        for (int n = 0; n < 16; n++) {
            o[n][0] *= al0; o[n][1] *= al0; o[n][2] *= al1; o[n][3] *= al1;
        }

        // ---- O += P V (bf16x3); P c-frag -> a-frag repack ----
        #pragma unroll
        for (int kc = 0; kc < 4; kc++) {
            uint32_t aPh[4], aPl[4];
            {
                float p00 = sc[2*kc][0],   p01 = sc[2*kc][1],   p02 = sc[2*kc][2],   p03 = sc[2*kc][3];
                float p10 = sc[2*kc+1][0], p11 = sc[2*kc+1][1], p12 = sc[2*kc+1][2], p13 = sc[2*kc+1][3];
                aPh[0] = pack_bf16(p00, p01); aPh[1] = pack_bf16(p02, p03);
                aPh[2] = pack_bf16(p10, p11); aPh[3] = pack_bf16(p12, p13);
                __nv_bfloat162* hp = (__nv_bfloat162*)aPh;
                aPl[0] = pack_bf16(p00 - __bfloat162float(hp[0].x), p01 - __bfloat162float(hp[0].y));
                aPl[1] = pack_bf16(p02 - __bfloat162float(hp[1].x), p03 - __bfloat162float(hp[1].y));
                aPl[2] = pack_bf16(p10 - __bfloat162float(hp[2].x), p11 - __bfloat162float(hp[2].y));
                aPl[3] = pack_bf16(p12 - __bfloat162float(hp[3].x), p13 - __bfloat162float(hp[3].y));
            }
            #pragma unroll
            for (int p = 0; p < 8; p++) {
                uint32_t vo = st0 + 32768 + SWZ((uint32_t)((b_row + p * 16) * 128 + kc * 32 + b_kb));
                uint32_t bH[4], bL[4];
                LDSM4(bH[0], bH[1], bH[2], bH[3], vo);
                LDSM4(bL[0], bL[1], bL[2], bL[3], vo + 16384);
                mma_bf16(o[2*p],   aPh, bH[0], bH[1]);
                mma_bf16(o[2*p],   aPh, bL[0], bL[1]);
                mma_bf16(o[2*p],   aPl, bH[0], bH[1]);
                mma_bf16(o[2*p+1], aPh, bH[2], bH[3]);
                mma_bf16(o[2*p+1], aPh, bL[2], bL[3]);
                mma_bf16(o[2*p+1], aPl, bH[2], bH[3]);
            }
        }
        __syncthreads();
        if (kb + 2 < NB) load_kv(kb + 2, s);
    }

    // ---- epilogue: 1/l, write yh/yl splits ----
    l0 += __shfl_xor_sync(0xffffffffu, l0, 1);
    l0 += __shfl_xor_sync(0xffffffffu, l0, 2);
    l1 += __shfl_xor_sync(0xffffffffu, l1, 1);
    l1 += __shfl_xor_sync(0xffffffffu, l1, 2);
    float i0 = 1.f / l0, i1 = 1.f / l1;
    const size_t rbase = (size_t)(b * L_ + row0) * D_ + h * HD_ + ec;
    #pragma unroll
    for (int n = 0; n < 16; n++) {
        float v0 = o[n][0] * i0, v1 = o[n][1] * i0;
        float v2 = o[n][2] * i1, v3 = o[n][3] * i1;
        size_t o0 = rbase + n * 8;
        size_t o1 = o0 + 8 * (size_t)D_;
        __nv_bfloat16 h0 = __float2bfloat16(v0), h1 = __float2bfloat16(v1);
        __nv_bfloat16 h2 = __float2bfloat16(v2), h3 = __float2bfloat16(v3);
        *(__nv_bfloat162*)(yh + o0) = __nv_bfloat162(h0, h1);
        *(__nv_bfloat162*)(yh + o1) = __nv_bfloat162(h2, h3);
        *(__nv_bfloat162*)(yl + o0) = __floats2bfloat162_rn(v0 - __bfloat162float(h0), v1 - __bfloat162float(h1));
        *(__nv_bfloat162*)(yl + o1) = __floats2bfloat162_rn(v2 - __bfloat162float(h2), v3 - __bfloat162float(h3));
    }
}

// ---------------------------------------------------------------------------
extern "C" void kernel_launch(void* const* d_in, const int* in_sizes, int n_in,
                              void* d_out, int out_size)
{
    const float* x     = (const float*)d_in[0];
    const float* w_qkv = (const float*)d_in[1];
    const float* w_o   = (const float*)d_in[2];
    float* out = (float*)d_out;

    float *qkv, *ct, *st;
    __nv_bfloat16 *xh, *xl, *wqh, *wql, *woh, *wol, *yh, *yl;
    __nv_bfloat16 *qh, *ql, *kh, *kl, *vth, *vtl;
    cudaGetSymbolAddress((void**)&qkv, g_qkv);
    cudaGetSymbolAddress((void**)&ct,  g_cos); cudaGetSymbolAddress((void**)&st, g_sin);
    cudaGetSymbolAddress((void**)&xh,  g_xh);  cudaGetSymbolAddress((void**)&xl, g_xl);
    cudaGetSymbolAddress((void**)&wqh, g_wqh); cudaGetSymbolAddress((void**)&wql, g_wql);
    cudaGetSymbolAddress((void**)&woh, g_woh); cudaGetSymbolAddress((void**)&wol, g_wol);
    cudaGetSymbolAddress((void**)&yh,  g_yh);  cudaGetSymbolAddress((void**)&yl, g_yl);
    cudaGetSymbolAddress((void**)&qh,  g_qh);  cudaGetSymbolAddress((void**)&ql, g_ql);
    cudaGetSymbolAddress((void**)&kh,  g_kh);  cudaGetSymbolAddress((void**)&kl, g_kl);
    cudaGetSymbolAddress((void**)&vth, g_vth); cudaGetSymbolAddress((void**)&vtl, g_vtl);

    cudaFuncSetAttribute(gemm_bf16x3, cudaFuncAttributeMaxDynamicSharedMemorySize, GEMM_SMEM);
    cudaFuncSetAttribute(flash_mma,   cudaFuncAttributeMaxDynamicSharedMemorySize, ATT_SMEM);

    // splits + rope table
    split_bf16<<<(M_ * D_ / 4) / 256, 256>>>(x, xh, xl, M_ * D_ / 4);
    split_bf16<<<(E3_ * D_ / 4) / 256, 256>>>(w_qkv, wqh, wql, E3_ * D_ / 4);
    split_bf16<<<(D_ * D_ / 4) / 256, 256>>>(w_o, woh, wol, D_ * D_ / 4);
    rope_table<<<(L_ * 64) / 256, 256>>>(ct, st);

    // 1) qkv = x @ w_qkv^T
    gemm_bf16x3<<<dim3(E3_ / BN, M_ / BM), 256, GEMM_SMEM>>>(xh, xl, wqh, wql, qkv, M_, E3_, D_);

    // 2) fused rope + split + relayout
    qkv_split<<<dim3(L_ / 32, B_ * H_), 256>>>(qkv, ct, st, qh, ql, kh, kl, vth, vtl);

    // 3) causal flash attention (bf16x3 mma) -> yh/yl
    flash_mma<<<dim3(L_ / 128, B_ * H_), 256, ATT_SMEM>>>(qh, ql, kh, kl, vth, vtl, yh, yl);

    // 4) out = y @ w_o^T
    gemm_bf16x3<<<dim3(D_ / BN, M_ / BM), 256, GEMM_SMEM>>>(yh, yl, woh, wol, out, M_, D_, D_);
}